// round 2
// baseline (speedup 1.0000x reference)
#include <cuda_runtime.h>
#include <cstdint>
#include <math.h>

// Problem dims (fixed)
#define Bb 128
#define Tt 512
#define Ee 1024
#define Hh 1024
#define Vv 1024
#define BT (Bb*Tt)
#define RC 64      // recurrence CTAs
#define RN 16      // N columns per recurrence CTA (RC*RN = Hh)

// -------- device-global scratch (allowed; no allocations) ----------------
__device__ float g_xp[(size_t)BT * Hh];     // 256 MB: input projections [T][B][H]
__device__ float g_h[2][Bb * Hh];           // h double buffer
__device__ unsigned int g_bar;              // recurrence step barrier counter

// -------- helpers --------------------------------------------------------
__device__ __forceinline__ uint32_t f2t(float x) {
    uint32_t u; asm("cvt.rna.tf32.f32 %0, %1;" : "=r"(u) : "f"(x));
    return u;
}
// split fp32 into tf32 hi + tf32 lo with a = hi + lo (to ~2^-22 rel)
__device__ __forceinline__ void split(float x, uint32_t& hi, uint32_t& lo) {
    uint32_t h = f2t(x);
    hi = h;
    lo = f2t(x - __uint_as_float(h));
}
__device__ __forceinline__ void cp16(float* s, const float* g) {
    uint32_t sa = (uint32_t)__cvta_generic_to_shared(s);
    asm volatile("cp.async.cg.shared.global [%0], [%1], 16;\n" :: "r"(sa), "l"(g));
}
__device__ __forceinline__ void cp_commit() { asm volatile("cp.async.commit_group;\n"); }
template<int N> __device__ __forceinline__ void cp_wait() {
    asm volatile("cp.async.wait_group %0;\n" :: "n"(N));
}
// m16n8k8 tf32 mma, D += A*B
__device__ __forceinline__ void mma8(float* c, const uint32_t* a, const uint32_t* b) {
    asm volatile(
        "mma.sync.aligned.m16n8k8.row.col.f32.tf32.tf32.f32 "
        "{%0,%1,%2,%3},{%4,%5,%6,%7},{%8,%9},{%0,%1,%2,%3};"
        : "+f"(c[0]), "+f"(c[1]), "+f"(c[2]), "+f"(c[3])
        : "r"(a[0]), "r"(a[1]), "r"(a[2]), "r"(a[3]), "r"(b[0]), "r"(b[1]));
}

// -------- init: reset barrier, copy h_init into g_h[0] -------------------
__global__ void init_k(const float* __restrict__ h0) {
    int i = blockIdx.x * blockDim.x + threadIdx.x;
    if (i == 0) g_bar = 0u;
    for (int j = i; j < Bb * Hh; j += gridDim.x * blockDim.x)
        g_h[0][j] = h0[j];
}

// -------- generic GEMM: C[m][n] = sum_k A[m][k]*W[n][k] + bias[n] --------
// Tile 128(M) x 64(N) x 32(K), 256 threads = 8 warps (4M x 2N), warp 32x32.
// A split to tf32 hi/lo in-register (2 mma per position); W rounded RNA.
// GATHER: A rows come from embed table via tokens (phase 1).
__device__ __forceinline__ void stage_tiles(const float* const* rowptr,
                                            const float* __restrict__ W,
                                            int n0, int k0,
                                            float* Asb, float* Bsb, int tid) {
    #pragma unroll
    for (int j = 0; j < 4; j++) {                 // A: 128 rows x 32 f32 = 1024 chunks
        int c = j * 256 + tid;
        int r = c >> 3, o = c & 7;
        cp16(Asb + r * 36 + o * 4, rowptr[r] + k0 + o * 4);
    }
    #pragma unroll
    for (int j = 0; j < 2; j++) {                 // B: 64 rows x 32 f32 = 512 chunks
        int c = j * 256 + tid;
        int r = c >> 3, o = c & 7;
        cp16(Bsb + r * 36 + o * 4, W + (size_t)(n0 + r) * 1024 + k0 + o * 4);
    }
}

template<bool GATHER>
__global__ __launch_bounds__(256, 2) void gemm_k(const float* __restrict__ Abase,
                                                 const int* __restrict__ tok,
                                                 const float* __restrict__ W,
                                                 const float* __restrict__ bias,
                                                 float* __restrict__ C) {
    extern __shared__ float sm[];
    float* As = sm;                         // 2 x 128 x 36
    float* Bs = sm + 9216;                  // 2 x 64 x 36
    const float** rowptr = (const float**)(sm + 13824);   // 128 ptrs

    const int tid = threadIdx.x;
    if (tid < 128) {
        if (GATHER) rowptr[tid] = Abase + (size_t)tok[tid * Tt + blockIdx.y] * Ee;
        else        rowptr[tid] = Abase + ((size_t)blockIdx.y * 128 + tid) * Hh;
    }
    __syncthreads();

    const int n0 = blockIdx.x * 64;
    const int lane = tid & 31, w = tid >> 5;
    const int g = lane >> 2, tig = lane & 3;
    const int wm = (w >> 1) * 32, wn = (w & 1) * 32;

    float acc[2][4][4];
    #pragma unroll
    for (int a = 0; a < 2; a++)
        #pragma unroll
        for (int b = 0; b < 4; b++)
            #pragma unroll
            for (int c = 0; c < 4; c++) acc[a][b][c] = 0.f;

    stage_tiles(rowptr, W, n0, 0, As, Bs, tid);
    cp_commit();

    for (int ks = 0; ks < 32; ks++) {
        int buf = ks & 1;
        if (ks < 31) {
            stage_tiles(rowptr, W, n0, (ks + 1) * 32,
                        As + (buf ^ 1) * 4608, Bs + (buf ^ 1) * 2304, tid);
            cp_commit();
            cp_wait<1>();
        } else {
            cp_wait<0>();
        }
        __syncthreads();

        const float* A_ = As + buf * 4608;
        const float* B_ = Bs + buf * 2304;
        #pragma unroll
        for (int kk = 0; kk < 32; kk += 8) {
            uint32_t ah[2][4], al[2][4];
            #pragma unroll
            for (int mi = 0; mi < 2; mi++) {
                int r = wm + mi * 16;
                split(A_[(r + g) * 36 + kk + tig],         ah[mi][0], al[mi][0]);
                split(A_[(r + g + 8) * 36 + kk + tig],     ah[mi][1], al[mi][1]);
                split(A_[(r + g) * 36 + kk + tig + 4],     ah[mi][2], al[mi][2]);
                split(A_[(r + g + 8) * 36 + kk + tig + 4], ah[mi][3], al[mi][3]);
            }
            uint32_t bb[4][2];
            #pragma unroll
            for (int ni = 0; ni < 4; ni++) {
                int n = wn + ni * 8 + g;
                bb[ni][0] = f2t(B_[n * 36 + kk + tig]);
                bb[ni][1] = f2t(B_[n * 36 + kk + tig + 4]);
            }
            #pragma unroll
            for (int mi = 0; mi < 2; mi++)
                #pragma unroll
                for (int ni = 0; ni < 4; ni++) {
                    mma8(acc[mi][ni], ah[mi], bb[ni]);
                    mma8(acc[mi][ni], al[mi], bb[ni]);
                }
        }
        __syncthreads();
    }

    // epilogue: + bias, store
    const int m0 = blockIdx.y * 128;
    #pragma unroll
    for (int ni = 0; ni < 4; ni++) {
        int nc = n0 + wn + ni * 8 + 2 * tig;
        float b0 = bias[nc], b1 = bias[nc + 1];
        #pragma unroll
        for (int mi = 0; mi < 2; mi++) {
            int r0 = m0 + wm + mi * 16 + g;
            *(float2*)&C[(size_t)r0 * 1024 + nc] =
                make_float2(acc[mi][ni][0] + b0, acc[mi][ni][1] + b1);
            *(float2*)&C[(size_t)(r0 + 8) * 1024 + nc] =
                make_float2(acc[mi][ni][2] + b0, acc[mi][ni][3] + b1);
        }
    }
}

// -------- persistent recurrence kernel -----------------------------------
// 64 CTAs x 256 threads. CTA c owns output cols [c*16, c*16+16).
// Wh slice (tf32-rounded) resident in smem. Per step: stage h (cp.async.cg,
// L1-bypass) in K=32 slices, 2-mma tf32 GEMM, tanh epilogue, atomic barrier.
__device__ __forceinline__ void stage_h(const float* hsrc, int ks, float* Asb, int tid) {
    int k0 = ks * 32;
    #pragma unroll
    for (int j = 0; j < 4; j++) {
        int c = j * 256 + tid;
        int r = c >> 3, o = c & 7;
        cp16(Asb + r * 36 + o * 4, hsrc + (size_t)r * 1024 + k0 + o * 4);
    }
}

__global__ __launch_bounds__(256, 1) void rnn_k(const float* __restrict__ Wh,
                                                const float* __restrict__ bh,
                                                float* __restrict__ h_e) {
    extern __shared__ float sm[];
    float* Whs = sm;                 // 16 x 1028 (tf32-rounded values)
    float* As  = sm + 16448;         // 2 x 128 x 36
    float* sbh = sm + 16448 + 9216;  // 16

    const int tid = threadIdx.x, cta = blockIdx.x;

    // load + round Wh slice once
    for (int i = tid; i < RN * 1024; i += 256) {
        int n = i >> 10, k = i & 1023;
        Whs[n * 1028 + k] = __uint_as_float(f2t(Wh[(size_t)(cta * RN + n) * 1024 + k]));
    }
    if (tid < RN) sbh[tid] = bh[cta * RN + tid];
    __syncthreads();

    const int lane = tid & 31, w = tid >> 5;
    const int g = lane >> 2, tig = lane & 3;

    for (int t = 0; t < Tt; t++) {
        const float* hsrc = g_h[t & 1];
        float* hdst = g_h[(t + 1) & 1];
        float acc[2][4] = {{0.f, 0.f, 0.f, 0.f}, {0.f, 0.f, 0.f, 0.f}};

        stage_h(hsrc, 0, As, tid);
        cp_commit();

        for (int ks = 0; ks < 32; ks++) {
            int buf = ks & 1;
            if (ks < 31) {
                stage_h(hsrc, ks + 1, As + (buf ^ 1) * 4608, tid);
                cp_commit();
                cp_wait<1>();
            } else {
                cp_wait<0>();
            }
            __syncthreads();

            const float* A_ = As + buf * 4608;
            #pragma unroll
            for (int kk = 0; kk < 32; kk += 8) {
                int kg = ks * 32 + kk;
                uint32_t ah[4], al[4];
                int r = w * 16;
                split(A_[(r + g) * 36 + kk + tig],         ah[0], al[0]);
                split(A_[(r + g + 8) * 36 + kk + tig],     ah[1], al[1]);
                split(A_[(r + g) * 36 + kk + tig + 4],     ah[2], al[2]);
                split(A_[(r + g + 8) * 36 + kk + tig + 4], ah[3], al[3]);
                #pragma unroll
                for (int nf = 0; nf < 2; nf++) {
                    uint32_t b[2];
                    b[0] = __float_as_uint(Whs[(nf * 8 + g) * 1028 + kg + tig]);
                    b[1] = __float_as_uint(Whs[(nf * 8 + g) * 1028 + kg + tig + 4]);
                    mma8(acc[nf], ah, b);
                    mma8(acc[nf], al, b);
                }
            }
            __syncthreads();
        }

        // epilogue: h = tanh(gemm + xp + bh); write h buffer + h_e output
        #pragma unroll
        for (int nf = 0; nf < 2; nf++) {
            int nloc = nf * 8 + 2 * tig;
            int gn = cta * RN + nloc;
            float b0 = sbh[nloc], b1 = sbh[nloc + 1];
            #pragma unroll
            for (int hh = 0; hh < 2; hh++) {
                int m = w * 16 + g + hh * 8;
                float2 xp = *(const float2*)&g_xp[(size_t)(t * 128 + m) * 1024 + gn];
                float v0 = tanhf(acc[nf][hh * 2 + 0] + xp.x + b0);
                float v1 = tanhf(acc[nf][hh * 2 + 1] + xp.y + b1);
                *(float2*)&hdst[(size_t)m * 1024 + gn] = make_float2(v0, v1);
                *(float2*)&h_e[((size_t)m * Tt + t) * 1024 + gn] = make_float2(v0, v1);
            }
        }

        // grid barrier (monotonic counter; reset each launch by init_k)
        __threadfence();
        __syncthreads();
        if (tid == 0) {
            atomicAdd(&g_bar, 1u);
            unsigned target = (unsigned)(RC * (t + 1));
            unsigned v;
            do {
                asm volatile("ld.acquire.gpu.u32 %0, [%1];" : "=r"(v) : "l"(&g_bar));
            } while (v < target);
        }
        __syncthreads();
    }
}

// -------- launch ---------------------------------------------------------
extern "C" void kernel_launch(void* const* d_in, const int* in_sizes, int n_in,
                              void* d_out, int out_size) {
    (void)in_sizes; (void)n_in; (void)out_size;
    const int*   x      = (const int*)d_in[0];
    const float* h_init = (const float*)d_in[1];
    const float* embed  = (const float*)d_in[2];
    const float* Wx     = (const float*)d_in[3];
    const float* bx     = (const float*)d_in[4];
    const float* Wh     = (const float*)d_in[5];
    const float* bh     = (const float*)d_in[6];
    const float* Wo     = (const float*)d_in[7];
    const float* bo     = (const float*)d_in[8];

    float* out = (float*)d_out;
    float* h_e = out;                       // [B][T][H]
    float* y_e = out + (size_t)BT * Hh;     // [B][T][V]

    const int SMEM_P = (9216 + 4608) * 4 + 128 * 8;        // 56320
    const int SMEM_R = (16448 + 9216 + 16) * 4;            // 102720

    cudaFuncSetAttribute(gemm_k<true>,  cudaFuncAttributeMaxDynamicSharedMemorySize, SMEM_P);
    cudaFuncSetAttribute(gemm_k<false>, cudaFuncAttributeMaxDynamicSharedMemorySize, SMEM_P);
    cudaFuncSetAttribute(rnn_k,         cudaFuncAttributeMaxDynamicSharedMemorySize, SMEM_R);

    void* xp_ptr = nullptr;
    cudaGetSymbolAddress(&xp_ptr, g_xp);

    // 1. reset barrier + h_init -> g_h[0]
    init_k<<<128, 256>>>(h_init);
    // 2. xp[t][b][:] = embed[x[b][t]] @ Wx^T + bx
    gemm_k<true><<<dim3(16, 512), 256, SMEM_P>>>(embed, x, Wx, bx, (float*)xp_ptr);
    // 3. serial recurrence -> h_e
    rnn_k<<<RC, 256, SMEM_R>>>(Wh, bh, h_e);
    // 4. y = h_e @ Wo^T + bo
    gemm_k<false><<<dim3(16, 512), 256, SMEM_P>>>(h_e, nullptr, Wo, bo, y_e);
}

// round 3
// speedup vs baseline: 1.3200x; 1.3200x over previous
#include <cuda_runtime.h>
#include <cstdint>
#include <math.h>

// Problem dims (fixed)
#define Bb 128
#define Tt 512
#define Hh 1024
#define BT (Bb*Tt)
#define RCg 64     // recurrence CTAs (each owns 16 output cols)

// -------- device-global scratch ------------------------------------------
__device__ float g_xp[(size_t)BT * Hh];    // 256 MB input projections [T][B][H]
__device__ float g_hr[(size_t)BT * Hh];    // 256 MB rounded+permuted h [B][T][H]
__device__ float g_h[2][Bb * Hh];          // h double buffer (rounded+permuted)
__device__ float g_embr[1024 * 1024];      // rounded+permuted embed table
__device__ float g_Wxr[1024 * 1024];       // rounded+permuted Wx
__device__ float g_Wor[1024 * 1024];       // rounded+permuted Wo
__device__ unsigned int g_bar;

// -------- helpers --------------------------------------------------------
__device__ __forceinline__ uint32_t f2t(float x) {
    uint32_t u; asm("cvt.rna.tf32.f32 %0, %1;" : "=r"(u) : "f"(x));
    return u;
}
__device__ __forceinline__ float rndt(float x) { return __uint_as_float(f2t(x)); }
// k-pair interleave within 8-blocks: (j, j+4) -> positions (2j, 2j+1)
__device__ __forceinline__ int pig(int k) {
    int j = k & 7;
    return (k & ~7) | ((j < 4) ? (2 * j) : (2 * (j - 4) + 1));
}
__device__ __forceinline__ void cp16(float* s, const float* g) {
    uint32_t sa = (uint32_t)__cvta_generic_to_shared(s);
    asm volatile("cp.async.cg.shared.global [%0], [%1], 16;\n" :: "r"(sa), "l"(g));
}
__device__ __forceinline__ void cp_commit() { asm volatile("cp.async.commit_group;\n"); }
template<int N> __device__ __forceinline__ void cp_wait() {
    asm volatile("cp.async.wait_group %0;\n" :: "n"(N));
}
__device__ __forceinline__ void mma8(float* c, const uint32_t* a, const uint32_t* b) {
    asm volatile(
        "mma.sync.aligned.m16n8k8.row.col.f32.tf32.tf32.f32 "
        "{%0,%1,%2,%3},{%4,%5,%6,%7},{%8,%9},{%0,%1,%2,%3};"
        : "+f"(c[0]), "+f"(c[1]), "+f"(c[2]), "+f"(c[3])
        : "r"(a[0]), "r"(a[1]), "r"(a[2]), "r"(a[3]), "r"(b[0]), "r"(b[1]));
}

// -------- prologue: round+permute embed, Wx, Wo --------------------------
__global__ void prep_k(const float* __restrict__ e, const float* __restrict__ wx,
                       const float* __restrict__ wo) {
    int st = gridDim.x * blockDim.x;
    for (int i = blockIdx.x * blockDim.x + threadIdx.x; i < 1024 * 1024; i += st) {
        int r = i >> 10, k = i & 1023;
        int d = (r << 10) | pig(k);
        g_embr[d] = rndt(e[i]);
        g_Wxr[d]  = rndt(wx[i]);
        g_Wor[d]  = rndt(wo[i]);
    }
}

__global__ void init_k(const float* __restrict__ h0) {
    int i = blockIdx.x * blockDim.x + threadIdx.x;
    if (i == 0) g_bar = 0u;
    for (int j = i; j < Bb * Hh; j += gridDim.x * blockDim.x) {
        int r = j >> 10, k = j & 1023;
        g_h[0][(r << 10) | pig(k)] = rndt(h0[j]);
    }
}

// -------- phase GEMM: C[m][n] = sum_k A[m][k]*W[n][k] + bias[n] ----------
// Tile 128x64xK32, 256 threads = 8 warps (4M x 2N) of 32x32.
// A and W pre-rounded (tf32 bits) and k-pair-interleaved -> LDS.64 frags, no cvt.
#define PS 44   // smem row stride (floats): mod32=12 -> conflict-free frag LDS.64

__device__ __forceinline__ void stage(const float* const* rp, const float* __restrict__ W,
                                      int n0, int k0, float* As, float* Bs, int tid) {
    #pragma unroll
    for (int j = 0; j < 4; j++) {                 // A: 128 rows x 32 floats
        int c = j * 256 + tid; int r = c >> 3, o = c & 7;
        cp16(As + r * PS + o * 4, rp[r] + k0 + o * 4);
    }
    #pragma unroll
    for (int j = 0; j < 2; j++) {                 // B: 64 rows x 32 floats
        int c = j * 256 + tid; int r = c >> 3, o = c & 7;
        cp16(Bs + r * PS + o * 4, W + (size_t)(n0 + r) * 1024 + k0 + o * 4);
    }
}

template<bool GATHER>
__global__ __launch_bounds__(256, 2) void gemm_k(const float* __restrict__ Ab,
                                                 const int* __restrict__ tok,
                                                 const float* __restrict__ W,
                                                 const float* __restrict__ bias,
                                                 float* __restrict__ C) {
    extern __shared__ float sm[];
    float* As = sm;                        // 2 x 128 x 44 = 11264
    float* Bs = sm + 11264;                // 2 x  64 x 44 = 5632
    const float** rp = (const float**)(sm + 16896);   // 128 ptrs

    const int tid = threadIdx.x;
    if (tid < 128) {
        if (GATHER) rp[tid] = Ab + (size_t)tok[tid * Tt + blockIdx.y] * 1024;
        else        rp[tid] = Ab + ((size_t)blockIdx.y * 128 + tid) * 1024;
    }
    __syncthreads();

    const int n0 = blockIdx.x * 64;
    const int lane = tid & 31, w = tid >> 5;
    const int g = lane >> 2, t4 = lane & 3;
    const int wm = (w >> 1) * 32, wn = (w & 1) * 32;

    float acc[2][4][4];
    #pragma unroll
    for (int a = 0; a < 2; a++)
        #pragma unroll
        for (int b = 0; b < 4; b++)
            #pragma unroll
            for (int c = 0; c < 4; c++) acc[a][b][c] = 0.f;

    stage(rp, W, n0, 0, As, Bs, tid);
    cp_commit();

    for (int ks = 0; ks < 32; ks++) {
        int buf = ks & 1;
        if (ks < 31) {
            stage(rp, W, n0, (ks + 1) * 32, As + (buf ^ 1) * 5632, Bs + (buf ^ 1) * 2816, tid);
            cp_commit();
            cp_wait<1>();
        } else {
            cp_wait<0>();
        }
        __syncthreads();

        const float* A_ = As + buf * 5632;
        const float* B_ = Bs + buf * 2816;
        #pragma unroll
        for (int kk = 0; kk < 32; kk += 8) {
            uint32_t a[2][4];
            #pragma unroll
            for (int mi = 0; mi < 2; mi++) {
                float2 p0 = *(const float2*)&A_[(wm + mi * 16 + g) * PS + kk + 2 * t4];
                float2 p1 = *(const float2*)&A_[(wm + mi * 16 + 8 + g) * PS + kk + 2 * t4];
                a[mi][0] = __float_as_uint(p0.x); a[mi][1] = __float_as_uint(p1.x);
                a[mi][2] = __float_as_uint(p0.y); a[mi][3] = __float_as_uint(p1.y);
            }
            #pragma unroll
            for (int ni = 0; ni < 4; ni++) {
                float2 q = *(const float2*)&B_[(wn + ni * 8 + g) * PS + kk + 2 * t4];
                uint32_t b[2] = { __float_as_uint(q.x), __float_as_uint(q.y) };
                mma8(acc[0][ni], a[0], b);
                mma8(acc[1][ni], a[1], b);
            }
        }
        __syncthreads();
    }

    const int m0 = blockIdx.y * 128;
    #pragma unroll
    for (int ni = 0; ni < 4; ni++) {
        int nc = n0 + wn + ni * 8 + 2 * t4;
        float b0 = bias[nc], b1 = bias[nc + 1];
        #pragma unroll
        for (int mi = 0; mi < 2; mi++) {
            int r0 = m0 + wm + mi * 16 + g;
            *(float2*)&C[(size_t)r0 * 1024 + nc] =
                make_float2(acc[mi][ni][0] + b0, acc[mi][ni][1] + b1);
            *(float2*)&C[(size_t)(r0 + 8) * 1024 + nc] =
                make_float2(acc[mi][ni][2] + b0, acc[mi][ni][3] + b1);
        }
    }
}

// -------- persistent recurrence kernel -----------------------------------
// 64 CTAs x 256 thr (8 warps). CTA owns 16 output cols. Warp w owns K-range
// [128w, 128w+128): computes full 128x16 partial, B (Wh slice) in smem read
// once/elem/step, A (h) streamed L2->regs via __ldcg (double buffered).
// Cross-warp reduce in smem, tanh epilogue, grid barrier per step.
#define WS 1036   // Whs row stride (mod32=12 -> conflict-free)
#define RS 20     // reduction row stride (16B-aligned float4 reads)

__global__ __launch_bounds__(256, 1) void rnn_k(const float* __restrict__ Wh,
                                                const float* __restrict__ bh,
                                                float* __restrict__ h_e) {
    extern __shared__ float sm[];
    float* Whs = sm;                 // 16 x 1036 = 16576 floats
    float* Red = sm + 16576;         // 8 x 128 x 20 = 20480 floats

    const int tid = threadIdx.x, cta = blockIdx.x;

    // build rounded+permuted Wh slice in smem (once)
    for (int i = tid; i < 16 * 1024; i += 256) {
        int n = i >> 10, k = i & 1023;
        Whs[n * WS + pig(k)] = rndt(Wh[(size_t)(cta * 16 + n) * 1024 + k]);
    }
    __syncthreads();

    const int lane = tid & 31, w = tid >> 5;
    const int g = lane >> 2, t4 = lane & 3;
    const int kb = w * 128;
    // epilogue mapping: thread -> row em, cols [gc, gc+8)
    const int em = tid >> 1, ecol = (tid & 1) * 8;
    const int gc = cta * 16 + ecol;
    const float4 bhA = *(const float4*)&bh[gc];
    const float4 bhB = *(const float4*)&bh[gc + 4];

    for (int t = 0; t < Tt; t++) {
        const float* hs = g_h[t & 1];
        float* hd = g_h[(t + 1) & 1];

        // prefetch xp for epilogue (latency hidden behind GEMM)
        float4 xpA = *(const float4*)&g_xp[(size_t)(t * 128 + em) * 1024 + gc];
        float4 xpB = *(const float4*)&g_xp[(size_t)(t * 128 + em) * 1024 + gc + 4];

        float acc[8][2][4];
        #pragma unroll
        for (int a = 0; a < 8; a++)
            #pragma unroll
            for (int b = 0; b < 2; b++)
                #pragma unroll
                for (int c = 0; c < 4; c++) acc[a][b][c] = 0.f;

        float2 Ac[16], An[16];
        #pragma unroll
        for (int mf = 0; mf < 8; mf++) {
            Ac[2 * mf]     = __ldcg((const float2*)&hs[(mf * 16 + g) * 1024 + kb + 2 * t4]);
            Ac[2 * mf + 1] = __ldcg((const float2*)&hs[(mf * 16 + 8 + g) * 1024 + kb + 2 * t4]);
        }
        #pragma unroll
        for (int kk = 0; kk < 128; kk += 8) {
            if (kk < 120) {
                #pragma unroll
                for (int mf = 0; mf < 8; mf++) {
                    An[2 * mf]     = __ldcg((const float2*)&hs[(mf * 16 + g) * 1024 + kb + kk + 8 + 2 * t4]);
                    An[2 * mf + 1] = __ldcg((const float2*)&hs[(mf * 16 + 8 + g) * 1024 + kb + kk + 8 + 2 * t4]);
                }
            }
            #pragma unroll
            for (int nf = 0; nf < 2; nf++) {
                float2 q = *(const float2*)&Whs[(nf * 8 + g) * WS + kb + kk + 2 * t4];
                uint32_t b[2] = { __float_as_uint(q.x), __float_as_uint(q.y) };
                #pragma unroll
                for (int mf = 0; mf < 8; mf++) {
                    uint32_t a[4] = { __float_as_uint(Ac[2 * mf].x), __float_as_uint(Ac[2 * mf + 1].x),
                                      __float_as_uint(Ac[2 * mf].y), __float_as_uint(Ac[2 * mf + 1].y) };
                    mma8(acc[mf][nf], a, b);
                }
            }
            #pragma unroll
            for (int i = 0; i < 16; i++) Ac[i] = An[i];
        }

        // write partials (warp-local K partials)
        #pragma unroll
        for (int mf = 0; mf < 8; mf++)
            #pragma unroll
            for (int nf = 0; nf < 2; nf++) {
                int m0 = mf * 16 + g, n0 = nf * 8 + 2 * t4;
                *(float2*)&Red[(w * 128 + m0) * RS + n0] =
                    make_float2(acc[mf][nf][0], acc[mf][nf][1]);
                *(float2*)&Red[(w * 128 + m0 + 8) * RS + n0] =
                    make_float2(acc[mf][nf][2], acc[mf][nf][3]);
            }
        __syncthreads();

        // reduce 8 partials -> epilogue
        float s[8] = {0.f, 0.f, 0.f, 0.f, 0.f, 0.f, 0.f, 0.f};
        #pragma unroll
        for (int ww = 0; ww < 8; ww++) {
            float4 r0 = *(const float4*)&Red[(ww * 128 + em) * RS + ecol];
            float4 r1 = *(const float4*)&Red[(ww * 128 + em) * RS + ecol + 4];
            s[0] += r0.x; s[1] += r0.y; s[2] += r0.z; s[3] += r0.w;
            s[4] += r1.x; s[5] += r1.y; s[6] += r1.z; s[7] += r1.w;
        }
        float v[8];
        v[0] = tanhf(s[0] + xpA.x + bhA.x);
        v[1] = tanhf(s[1] + xpA.y + bhA.y);
        v[2] = tanhf(s[2] + xpA.z + bhA.z);
        v[3] = tanhf(s[3] + xpA.w + bhA.w);
        v[4] = tanhf(s[4] + xpB.x + bhB.x);
        v[5] = tanhf(s[5] + xpB.y + bhB.y);
        v[6] = tanhf(s[6] + xpB.z + bhB.z);
        v[7] = tanhf(s[7] + xpB.w + bhB.w);

        // exact h_e output (natural order)
        size_t orow = ((size_t)em * Tt + t) * 1024 + gc;
        *(float4*)&h_e[orow]     = make_float4(v[0], v[1], v[2], v[3]);
        *(float4*)&h_e[orow + 4] = make_float4(v[4], v[5], v[6], v[7]);

        // rounded + k-pair-permuted copies: recurrence state + phase-3 input
        float r[8];
        #pragma unroll
        for (int j = 0; j < 8; j++) r[j] = rndt(v[j]);
        float4 pA = make_float4(r[0], r[4], r[1], r[5]);
        float4 pB = make_float4(r[2], r[6], r[3], r[7]);
        *(float4*)&g_hr[orow]     = pA;
        *(float4*)&g_hr[orow + 4] = pB;
        *(float4*)&hd[em * 1024 + gc]     = pA;
        *(float4*)&hd[em * 1024 + gc + 4] = pB;

        // grid barrier (monotonic counter; reset each launch by init_k)
        __threadfence();
        __syncthreads();
        if (tid == 0) {
            atomicAdd(&g_bar, 1u);
            unsigned tgt = (unsigned)(RCg * (t + 1)), vv;
            do {
                asm volatile("ld.acquire.gpu.u32 %0, [%1];" : "=r"(vv) : "l"(&g_bar));
            } while (vv < tgt);
        }
        __syncthreads();
    }
}

// -------- launch ---------------------------------------------------------
extern "C" void kernel_launch(void* const* d_in, const int* in_sizes, int n_in,
                              void* d_out, int out_size) {
    (void)in_sizes; (void)n_in; (void)out_size;
    const int*   x      = (const int*)d_in[0];
    const float* h_init = (const float*)d_in[1];
    const float* embed  = (const float*)d_in[2];
    const float* Wx     = (const float*)d_in[3];
    const float* bx     = (const float*)d_in[4];
    const float* Wh     = (const float*)d_in[5];
    const float* bh     = (const float*)d_in[6];
    const float* Wo     = (const float*)d_in[7];
    const float* bo     = (const float*)d_in[8];

    float* out = (float*)d_out;
    float* h_e = out;                       // [B][T][H]
    float* y_e = out + (size_t)BT * Hh;     // [B][T][V]

    const int SMEM_P = 16896 * 4 + 128 * 8;                 // 68608
    const int SMEM_R = (16576 + 20480) * 4;                 // 148224

    cudaFuncSetAttribute(gemm_k<true>,  cudaFuncAttributeMaxDynamicSharedMemorySize, SMEM_P);
    cudaFuncSetAttribute(gemm_k<false>, cudaFuncAttributeMaxDynamicSharedMemorySize, SMEM_P);
    cudaFuncSetAttribute(rnn_k,         cudaFuncAttributeMaxDynamicSharedMemorySize, SMEM_R);

    void* xp_ptr = nullptr;   cudaGetSymbolAddress(&xp_ptr, g_xp);
    void* hr_ptr = nullptr;   cudaGetSymbolAddress(&hr_ptr, g_hr);
    void* emb_ptr = nullptr;  cudaGetSymbolAddress(&emb_ptr, g_embr);
    void* wx_ptr = nullptr;   cudaGetSymbolAddress(&wx_ptr, g_Wxr);
    void* wo_ptr = nullptr;   cudaGetSymbolAddress(&wo_ptr, g_Wor);

    // 1. round+permute embed/Wx/Wo; reset barrier; h_init -> g_h[0]
    prep_k<<<512, 256>>>(embed, Wx, Wo);
    init_k<<<128, 256>>>(h_init);
    // 2. xp[t][b][:] = embed_r[x[b][t]] @ Wx_r^T + bx
    gemm_k<true><<<dim3(16, 512), 256, SMEM_P>>>((const float*)emb_ptr, x,
                                                 (const float*)wx_ptr, bx, (float*)xp_ptr);
    // 3. serial recurrence -> h_e (+ rounded copies)
    rnn_k<<<RCg, 256, SMEM_R>>>(Wh, bh, h_e);
    // 4. y = h_r @ Wo_r^T + bo
    gemm_k<false><<<dim3(16, 512), 256, SMEM_P>>>((const float*)hr_ptr, nullptr,
                                                  (const float*)wo_ptr, bo, y_e);
}